// round 12
// baseline (speedup 1.0000x reference)
#include <cuda_runtime.h>
#include <cstdint>

// LBFGS via Gram reformulation (3 launches, no atomics, no tcgen05 --
// harness PTX targets compute_103, arch-specific tensor ops unavailable).
//   K1: fused E=S.Y^T / F=Y.Y^T partials per (batch, kgroup), f32x2 4x4
//       register tiles, cp.async double-buffered K-chunks (DRAM hidden),
//       __launch_bounds__(256,3) for 24 warps/SM.
//   K2: sum 8 partials, warp triangular solves -> g*a, c, g.
//   K3: out = g*frc + sum (g a_j) y_j - sum c_i s_i.

#define MM 32
#define BB 64
#define DD 8192

#define NG 8                      // K-groups
#define KG (DD / NG)              // 1024 floats per CTA
#define SUB 128                   // K-chunk per pipeline stage
#define NSUB (KG / SUB)           // 8
#define ST 132                    // padded smem row stride (floats)
#define TILEF (32 * ST)           // 4224 floats per matrix tile
#define BUFF (2 * TILEF + SUB)    // floats per stage: S tile + Y tile + frc
#define K1_SMEM (2 * BUFF * 4)    // 68608 B (reduction scratch aliases this)

#define CH3 1024
#define NCH3 (DD / CH3)           // 8

typedef unsigned long long u64;

// ---------------- device scratch (static: no allocation) ----------------
__device__ float gEp[NG * BB * MM * MM];
__device__ float gFp[NG * BB * MM * MM];
__device__ float gwp[NG * BB * MM];
__device__ float gup[NG * BB * MM];
__device__ float gya[BB * MM];
__device__ float gcc[BB * MM];
__device__ float gg[BB];

// ---------------- helpers ----------------
__device__ __forceinline__ u64 pk2(float a, float b) {
    u64 r; asm("mov.b64 %0, {%1,%2};" : "=l"(r) : "f"(a), "f"(b)); return r;
}
__device__ __forceinline__ float2 upk2(u64 v) {
    float2 f; asm("mov.b64 {%0,%1}, %2;" : "=f"(f.x), "=f"(f.y) : "l"(v)); return f;
}
__device__ __forceinline__ u64 fma2(u64 a, u64 b, u64 c) {
    u64 d; asm("fma.rn.f32x2 %0, %1, %2, %3;" : "=l"(d) : "l"(a), "l"(b), "l"(c)); return d;
}
__device__ __forceinline__ float dot4(float4 a, float4 b) {
    return a.x * b.x + a.y * b.y + a.z * b.z + a.w * b.w;
}
__device__ __forceinline__ void cp16(void* smem_dst, const void* gsrc) {
    uint32_t d = (uint32_t)__cvta_generic_to_shared(smem_dst);
    asm volatile("cp.async.cg.shared.global [%0], [%1], 16;"
                 :: "r"(d), "l"(gsrc) : "memory");
}
__device__ __forceinline__ void cp_commit() {
    asm volatile("cp.async.commit_group;" ::: "memory");
}
template <int N>
__device__ __forceinline__ void cp_wait() {
    asm volatile("cp.async.wait_group %0;" :: "n"(N) : "memory");
}

// ---------------- K1: fused Gram partials, pipelined ----------------
__global__ __launch_bounds__(256, 3)
void k1_gram(const float* __restrict__ S, const float* __restrict__ Y,
             const float* __restrict__ FRC) {
    extern __shared__ __align__(1024) float smem[];

    const int b   = blockIdx.x >> 3;
    const int grp = blockIdx.x & 7;
    const int tid = threadIdx.x;

    const int tile = tid & 63;
    const int dq   = tid >> 6;
    const int i0   = tile >> 3;
    const int j0   = tile & 7;
    const int dbase = dq * 32;      // this dq's quarter of the 128-float chunk

    const int wrp  = tid >> 5;
    const int lane = tid & 31;

    // stage loader: S tile, Y tile, frc chunk via cp.async (no registers)
    auto load_stage = [&](int sub, float* buf) {
        const size_t cbase = (size_t)grp * KG + (size_t)sub * SUB;
#pragma unroll
        for (int r = 0; r < 4; ++r) {
            const int idx = r * 256 + tid;
            const int row = idx >> 5;          // 32 float4 per row
            const int c4  = idx & 31;
            const size_t g = ((size_t)row * BB + b) * DD + cbase + c4 * 4;
            cp16(&buf[row * ST + c4 * 4],         S + g);
            cp16(&buf[TILEF + row * ST + c4 * 4], Y + g);
        }
        if (tid < 32)
            cp16(&buf[2 * TILEF + tid * 4], FRC + (size_t)b * DD + cbase + tid * 4);
        cp_commit();
    };

    u64 accE[16], accF[16];
#pragma unroll
    for (int n = 0; n < 16; ++n) { accE[n] = 0ull; accF[n] = 0ull; }
    float tw[4] = {0.f, 0.f, 0.f, 0.f};
    float tu[4] = {0.f, 0.f, 0.f, 0.f};

    load_stage(0, smem);

#pragma unroll 1
    for (int t = 0; t < NSUB; ++t) {
        float* cur = smem + (t & 1) * BUFF;
        float* nxt = smem + ((t + 1) & 1) * BUFF;

        if (t + 1 < NSUB) { load_stage(t + 1, nxt); cp_wait<1>(); }
        else              { cp_wait<0>(); }
        __syncthreads();   // stage t visible to all

        const float* cS = cur;
        const float* cY = cur + TILEF;
        const float* cF = cur + 2 * TILEF;

#pragma unroll
        for (int d4 = 0; d4 < 8; ++d4) {
            const int c = dbase + d4 * 4;
            ulonglong2 yu[4];
#pragma unroll
            for (int l = 0; l < 4; ++l)
                yu[l] = *(const ulonglong2*)&cY[(j0 + 8 * l) * ST + c];
#pragma unroll
            for (int k = 0; k < 4; ++k) {
                ulonglong2 su = *(const ulonglong2*)&cS[(i0 + 8 * k) * ST + c];
                ulonglong2 zu = *(const ulonglong2*)&cY[(i0 + 8 * k) * ST + c];
#pragma unroll
                for (int l = 0; l < 4; ++l) {
                    accE[k * 4 + l] = fma2(su.x, yu[l].x, accE[k * 4 + l]);
                    accE[k * 4 + l] = fma2(su.y, yu[l].y, accE[k * 4 + l]);
                    accF[k * 4 + l] = fma2(zu.x, yu[l].x, accF[k * 4 + l]);
                    accF[k * 4 + l] = fma2(zu.y, yu[l].y, accF[k * 4 + l]);
                }
            }
        }

        // w/u partial dots (warp wrp: rows wrp, wrp+8, wrp+16, wrp+24)
#pragma unroll
        for (int m = 0; m < 4; ++m) {
            const int i = wrp + 8 * m;
            float4 a  = *(const float4*)&cS[i * ST + lane * 4];
            float4 bb = *(const float4*)&cY[i * ST + lane * 4];
            float4 ff = *(const float4*)&cF[lane * 4];
            tw[m] += dot4(a, ff);
            tu[m] += dot4(bb, ff);
        }
        __syncthreads();   // stage consumed; t+1 iteration may overwrite cur
    }

    // ---- cross-dq reduction in smem (aliases the ring), plain STG ----
    float* sRed = smem;    // 4 dq x 64 tiles x 16 = 4096 floats
    {
        float* myE = sRed + (dq * 64 + tile) * 16;
#pragma unroll
        for (int n = 0; n < 16; ++n) {
            float2 p = upk2(accE[n]);
            myE[n] = p.x + p.y;
        }
    }
    __syncthreads();
    {
        float* outE = gEp + ((size_t)grp * BB + b) * (MM * MM);
#pragma unroll
        for (int e = 0; e < 4; ++e) {
            const int el = tid + e * 256;          // el < 1024
            const int I = el >> 5, J = el & 31;
            const int ti = (I & 7) * 8 + (J & 7);
            const int kl = (I >> 3) * 4 + (J >> 3);
            float v = sRed[(0 * 64 + ti) * 16 + kl] + sRed[(1 * 64 + ti) * 16 + kl]
                    + sRed[(2 * 64 + ti) * 16 + kl] + sRed[(3 * 64 + ti) * 16 + kl];
            outE[el] = v;
        }
    }
    __syncthreads();
    {
        float* myF = sRed + (dq * 64 + tile) * 16;
#pragma unroll
        for (int n = 0; n < 16; ++n) {
            float2 p = upk2(accF[n]);
            myF[n] = p.x + p.y;
        }
    }
    __syncthreads();
    {
        float* outF = gFp + ((size_t)grp * BB + b) * (MM * MM);
#pragma unroll
        for (int e = 0; e < 4; ++e) {
            const int el = tid + e * 256;
            const int I = el >> 5, J = el & 31;
            const int ti = (I & 7) * 8 + (J & 7);
            const int kl = (I >> 3) * 4 + (J >> 3);
            float v = sRed[(0 * 64 + ti) * 16 + kl] + sRed[(1 * 64 + ti) * 16 + kl]
                    + sRed[(2 * 64 + ti) * 16 + kl] + sRed[(3 * 64 + ti) * 16 + kl];
            outF[el] = v;
        }
    }

    // w/u: shfl-reduce, lane0 writes the 4 rows this warp owns
#pragma unroll
    for (int m = 0; m < 4; ++m) {
#pragma unroll
        for (int off = 16; off > 0; off >>= 1) {
            tw[m] += __shfl_xor_sync(0xffffffffu, tw[m], off);
            tu[m] += __shfl_xor_sync(0xffffffffu, tu[m], off);
        }
    }
    if (lane == 0) {
        float* ow = gwp + ((size_t)grp * BB + b) * MM;
        float* ou = gup + ((size_t)grp * BB + b) * MM;
#pragma unroll
        for (int m = 0; m < 4; ++m) {
            ow[wrp + 8 * m] = tw[m];
            ou[wrp + 8 * m] = tu[m];
        }
    }
}

// ---------------- K2: reduce partials + full scalar solve ----------------
__global__ __launch_bounds__(256)
void k2_solve(void) {
    __shared__ float sE[MM * MM];
    __shared__ float sF[MM * MM];

    const int b   = blockIdx.x;
    const int tid = threadIdx.x;

    {
        float4 aE = make_float4(0.f, 0.f, 0.f, 0.f);
        float4 aF = aE;
#pragma unroll
        for (int g = 0; g < NG; ++g) {
            const size_t base4 = ((size_t)g * BB + b) * (MM * MM / 4) + tid;
            float4 e = ((const float4*)gEp)[base4];
            float4 f = ((const float4*)gFp)[base4];
            aE.x += e.x; aE.y += e.y; aE.z += e.z; aE.w += e.w;
            aF.x += f.x; aF.y += f.y; aF.z += f.z; aF.w += f.w;
        }
        ((float4*)sE)[tid] = aE;
        ((float4*)sF)[tid] = aF;
    }
    __syncthreads();

    if (tid >= 32) return;
    const int j = tid;

    float w_own = 0.f, u_own = 0.f;
#pragma unroll
    for (int g = 0; g < NG; ++g) {
        w_own += gwp[((size_t)g * BB + b) * MM + j];
        u_own += gup[((size_t)g * BB + b) * MM + j];
    }

    // backward solve for a (thread j holds E column j)
    float ecol[MM];
#pragma unroll
    for (int i = 0; i < MM; ++i) ecol[i] = sE[i * MM + j];
    float a_own = 0.0f, r_own = 0.0f;
#pragma unroll
    for (int ii = 0; ii < MM; ++ii) {
        const int i = MM - 1 - ii;
        float contrib = (j > i) ? a_own * ecol[i] : 0.0f;
#pragma unroll
        for (int off = 16; off > 0; off >>= 1)
            contrib += __shfl_xor_sync(0xffffffffu, contrib, off);
        const float ediag = __shfl_sync(0xffffffffu, ecol[i], i);
        const float wi    = __shfl_sync(0xffffffffu, w_own, i);
        const float ai    = (-wi - contrib) / ediag;
        if (j == i) { a_own = ai; r_own = 1.0f / ediag; }
    }

    const float g = sE[(MM - 1) * MM + (MM - 1)] / sF[(MM - 1) * MM + (MM - 1)];

    // v_j = -u_j - sum_i a_i F[j][i]
    float v_own = -u_own;
#pragma unroll
    for (int q = 0; q < 8; ++q) {
        float4 fv = *(const float4*)&sF[j * MM + q * 4];
        v_own -= __shfl_sync(0xffffffffu, a_own, q * 4 + 0) * fv.x;
        v_own -= __shfl_sync(0xffffffffu, a_own, q * 4 + 1) * fv.y;
        v_own -= __shfl_sync(0xffffffffu, a_own, q * 4 + 2) * fv.z;
        v_own -= __shfl_sync(0xffffffffu, a_own, q * 4 + 3) * fv.w;
    }

    // forward solve for c (thread j holds E row j)
    float erow[MM];
#pragma unroll
    for (int q = 0; q < 8; ++q) {
        float4 v = *(const float4*)&sE[j * MM + q * 4];
        erow[q * 4 + 0] = v.x; erow[q * 4 + 1] = v.y;
        erow[q * 4 + 2] = v.z; erow[q * 4 + 3] = v.w;
    }
    float c_own = 0.0f;
#pragma unroll
    for (int i = 0; i < MM; ++i) {
        float contrib = (j < i) ? c_own * erow[i] : 0.0f;
#pragma unroll
        for (int off = 16; off > 0; off >>= 1)
            contrib += __shfl_xor_sync(0xffffffffu, contrib, off);
        const float ri = __shfl_sync(0xffffffffu, r_own, i);
        const float ai = __shfl_sync(0xffffffffu, a_own, i);
        const float vi = __shfl_sync(0xffffffffu, v_own, i);
        const float ci = ai - ri * (g * vi + contrib);
        if (j == i) c_own = ci;
    }

    gya[b * MM + j] = g * a_own;
    gcc[b * MM + j] = c_own;
    if (j == 0) gg[b] = g;
}

// ---------------- K3: out = g frc + sum (g a_j) y_j - sum c_i s_i --------
__global__ __launch_bounds__(256)
void k3_out(const float* __restrict__ S, const float* __restrict__ Y,
            const float* __restrict__ FRC, float* __restrict__ OUT) {
    __shared__ float sya[MM];
    __shared__ float scc[MM];
    __shared__ float sg[1];

    const int b  = blockIdx.x >> 3;
    const int ch = blockIdx.x & 7;
    const int tid = threadIdx.x;

    if (tid < MM) { sya[tid] = gya[b * MM + tid]; scc[tid] = gcc[b * MM + tid]; }
    if (tid == MM) sg[0] = gg[b];
    __syncthreads();

    const size_t d0 = (size_t)ch * CH3 + tid * 4;
    const float g = sg[0];
    float4 f = *(const float4*)(FRC + (size_t)b * DD + d0);
    u64 acc0 = pk2(g * f.x, g * f.y);
    u64 acc1 = pk2(g * f.z, g * f.w);

#pragma unroll
    for (int j = 0; j < MM; ++j) {
        ulonglong2 yv = *(const ulonglong2*)(Y + ((size_t)j * BB + b) * DD + d0);
        const float cv = sya[j];
        const u64 cc = pk2(cv, cv);
        acc0 = fma2(cc, yv.x, acc0);
        acc1 = fma2(cc, yv.y, acc1);
    }
#pragma unroll
    for (int i = 0; i < MM; ++i) {
        ulonglong2 sv = *(const ulonglong2*)(S + ((size_t)i * BB + b) * DD + d0);
        const float cv = -scc[i];
        const u64 cc = pk2(cv, cv);
        acc0 = fma2(cc, sv.x, acc0);
        acc1 = fma2(cc, sv.y, acc1);
    }

    float2 o0 = upk2(acc0), o1 = upk2(acc1);
    float4 o; o.x = o0.x; o.y = o0.y; o.z = o1.x; o.w = o1.y;
    *(float4*)(OUT + (size_t)b * DD + d0) = o;
}

// ---------------- launch ----------------
extern "C" void kernel_launch(void* const* d_in, const int* in_sizes, int n_in,
                              void* d_out, int out_size) {
    const float* S   = (const float*)d_in[0];  // (M, B, D)
    const float* Y   = (const float*)d_in[1];  // (M, B, D)
    const float* FRC = (const float*)d_in[2];  // (B, D)
    float* OUT = (float*)d_out;                // (B, D)

    static bool attr_set = false;
    if (!attr_set) {
        cudaFuncSetAttribute(k1_gram,
                             cudaFuncAttributeMaxDynamicSharedMemorySize,
                             K1_SMEM);
        attr_set = true;
    }

    k1_gram<<<BB * NG, 256, K1_SMEM>>>(S, Y, FRC);
    k2_solve<<<BB, 256>>>();
    k3_out<<<BB * NCH3, 256>>>(S, Y, FRC, OUT);
}

// round 13
// speedup vs baseline: 1.0020x; 1.0020x over previous
#include <cuda_runtime.h>
#include <cstdint>

// LBFGS via Gram reformulation (3 launches, no atomics, no tcgen05 --
// harness PTX targets compute_103, arch-specific tensor ops unavailable).
//   K1: fused E=S.Y^T / F=Y.Y^T partials per (batch, kgroup), f32x2 4x4
//       register tiles, cp.async double-buffered K-chunks (DRAM hidden),
//       __launch_bounds__(256,3) for 24 warps/SM.
//   K2: sum 8 partials, warp triangular solves -> g*a, c, g.
//   K3: out = g*frc + sum (g a_j) y_j - sum c_i s_i.

#define MM 32
#define BB 64
#define DD 8192

#define NG 8                      // K-groups
#define KG (DD / NG)              // 1024 floats per CTA
#define SUB 128                   // K-chunk per pipeline stage
#define NSUB (KG / SUB)           // 8
#define ST 132                    // padded smem row stride (floats)
#define TILEF (32 * ST)           // 4224 floats per matrix tile
#define BUFF (2 * TILEF + SUB)    // floats per stage: S tile + Y tile + frc
#define K1_SMEM (2 * BUFF * 4)    // 68608 B (reduction scratch aliases this)

#define CH3 1024
#define NCH3 (DD / CH3)           // 8

typedef unsigned long long u64;

// ---------------- device scratch (static: no allocation) ----------------
__device__ float gEp[NG * BB * MM * MM];
__device__ float gFp[NG * BB * MM * MM];
__device__ float gwp[NG * BB * MM];
__device__ float gup[NG * BB * MM];
__device__ float gya[BB * MM];
__device__ float gcc[BB * MM];
__device__ float gg[BB];

// ---------------- helpers ----------------
__device__ __forceinline__ u64 pk2(float a, float b) {
    u64 r; asm("mov.b64 %0, {%1,%2};" : "=l"(r) : "f"(a), "f"(b)); return r;
}
__device__ __forceinline__ float2 upk2(u64 v) {
    float2 f; asm("mov.b64 {%0,%1}, %2;" : "=f"(f.x), "=f"(f.y) : "l"(v)); return f;
}
__device__ __forceinline__ u64 fma2(u64 a, u64 b, u64 c) {
    u64 d; asm("fma.rn.f32x2 %0, %1, %2, %3;" : "=l"(d) : "l"(a), "l"(b), "l"(c)); return d;
}
__device__ __forceinline__ float dot4(float4 a, float4 b) {
    return a.x * b.x + a.y * b.y + a.z * b.z + a.w * b.w;
}
__device__ __forceinline__ void cp16(void* smem_dst, const void* gsrc) {
    uint32_t d = (uint32_t)__cvta_generic_to_shared(smem_dst);
    asm volatile("cp.async.cg.shared.global [%0], [%1], 16;"
                 :: "r"(d), "l"(gsrc) : "memory");
}
__device__ __forceinline__ void cp_commit() {
    asm volatile("cp.async.commit_group;" ::: "memory");
}
template <int N>
__device__ __forceinline__ void cp_wait() {
    asm volatile("cp.async.wait_group %0;" :: "n"(N) : "memory");
}

// ---------------- K1: fused Gram partials, pipelined ----------------
__global__ __launch_bounds__(256, 3)
void k1_gram(const float* __restrict__ S, const float* __restrict__ Y,
             const float* __restrict__ FRC) {
    extern __shared__ __align__(1024) float smem[];

    const int b   = blockIdx.x >> 3;
    const int grp = blockIdx.x & 7;
    const int tid = threadIdx.x;

    const int tile = tid & 63;
    const int dq   = tid >> 6;
    const int i0   = tile >> 3;
    const int j0   = tile & 7;
    const int dbase = dq * 32;      // this dq's quarter of the 128-float chunk

    const int wrp  = tid >> 5;
    const int lane = tid & 31;

    // stage loader: S tile, Y tile, frc chunk via cp.async (no registers)
    auto load_stage = [&](int sub, float* buf) {
        const size_t cbase = (size_t)grp * KG + (size_t)sub * SUB;
#pragma unroll
        for (int r = 0; r < 4; ++r) {
            const int idx = r * 256 + tid;
            const int row = idx >> 5;          // 32 float4 per row
            const int c4  = idx & 31;
            const size_t g = ((size_t)row * BB + b) * DD + cbase + c4 * 4;
            cp16(&buf[row * ST + c4 * 4],         S + g);
            cp16(&buf[TILEF + row * ST + c4 * 4], Y + g);
        }
        if (tid < 32)
            cp16(&buf[2 * TILEF + tid * 4], FRC + (size_t)b * DD + cbase + tid * 4);
        cp_commit();
    };

    u64 accE[16], accF[16];
#pragma unroll
    for (int n = 0; n < 16; ++n) { accE[n] = 0ull; accF[n] = 0ull; }
    float tw[4] = {0.f, 0.f, 0.f, 0.f};
    float tu[4] = {0.f, 0.f, 0.f, 0.f};

    load_stage(0, smem);

#pragma unroll 1
    for (int t = 0; t < NSUB; ++t) {
        float* cur = smem + (t & 1) * BUFF;
        float* nxt = smem + ((t + 1) & 1) * BUFF;

        if (t + 1 < NSUB) { load_stage(t + 1, nxt); cp_wait<1>(); }
        else              { cp_wait<0>(); }
        __syncthreads();   // stage t visible to all

        const float* cS = cur;
        const float* cY = cur + TILEF;
        const float* cF = cur + 2 * TILEF;

#pragma unroll
        for (int d4 = 0; d4 < 8; ++d4) {
            const int c = dbase + d4 * 4;
            ulonglong2 yu[4];
#pragma unroll
            for (int l = 0; l < 4; ++l)
                yu[l] = *(const ulonglong2*)&cY[(j0 + 8 * l) * ST + c];
#pragma unroll
            for (int k = 0; k < 4; ++k) {
                ulonglong2 su = *(const ulonglong2*)&cS[(i0 + 8 * k) * ST + c];
                ulonglong2 zu = *(const ulonglong2*)&cY[(i0 + 8 * k) * ST + c];
#pragma unroll
                for (int l = 0; l < 4; ++l) {
                    accE[k * 4 + l] = fma2(su.x, yu[l].x, accE[k * 4 + l]);
                    accE[k * 4 + l] = fma2(su.y, yu[l].y, accE[k * 4 + l]);
                    accF[k * 4 + l] = fma2(zu.x, yu[l].x, accF[k * 4 + l]);
                    accF[k * 4 + l] = fma2(zu.y, yu[l].y, accF[k * 4 + l]);
                }
            }
        }

        // w/u partial dots (warp wrp: rows wrp, wrp+8, wrp+16, wrp+24)
#pragma unroll
        for (int m = 0; m < 4; ++m) {
            const int i = wrp + 8 * m;
            float4 a  = *(const float4*)&cS[i * ST + lane * 4];
            float4 bb = *(const float4*)&cY[i * ST + lane * 4];
            float4 ff = *(const float4*)&cF[lane * 4];
            tw[m] += dot4(a, ff);
            tu[m] += dot4(bb, ff);
        }
        __syncthreads();   // stage consumed; t+1 iteration may overwrite cur
    }

    // ---- cross-dq reduction in smem (aliases the ring), plain STG ----
    float* sRed = smem;    // 4 dq x 64 tiles x 16 = 4096 floats
    {
        float* myE = sRed + (dq * 64 + tile) * 16;
#pragma unroll
        for (int n = 0; n < 16; ++n) {
            float2 p = upk2(accE[n]);
            myE[n] = p.x + p.y;
        }
    }
    __syncthreads();
    {
        float* outE = gEp + ((size_t)grp * BB + b) * (MM * MM);
#pragma unroll
        for (int e = 0; e < 4; ++e) {
            const int el = tid + e * 256;          // el < 1024
            const int I = el >> 5, J = el & 31;
            const int ti = (I & 7) * 8 + (J & 7);
            const int kl = (I >> 3) * 4 + (J >> 3);
            float v = sRed[(0 * 64 + ti) * 16 + kl] + sRed[(1 * 64 + ti) * 16 + kl]
                    + sRed[(2 * 64 + ti) * 16 + kl] + sRed[(3 * 64 + ti) * 16 + kl];
            outE[el] = v;
        }
    }
    __syncthreads();
    {
        float* myF = sRed + (dq * 64 + tile) * 16;
#pragma unroll
        for (int n = 0; n < 16; ++n) {
            float2 p = upk2(accF[n]);
            myF[n] = p.x + p.y;
        }
    }
    __syncthreads();
    {
        float* outF = gFp + ((size_t)grp * BB + b) * (MM * MM);
#pragma unroll
        for (int e = 0; e < 4; ++e) {
            const int el = tid + e * 256;
            const int I = el >> 5, J = el & 31;
            const int ti = (I & 7) * 8 + (J & 7);
            const int kl = (I >> 3) * 4 + (J >> 3);
            float v = sRed[(0 * 64 + ti) * 16 + kl] + sRed[(1 * 64 + ti) * 16 + kl]
                    + sRed[(2 * 64 + ti) * 16 + kl] + sRed[(3 * 64 + ti) * 16 + kl];
            outF[el] = v;
        }
    }

    // w/u: shfl-reduce, lane0 writes the 4 rows this warp owns
#pragma unroll
    for (int m = 0; m < 4; ++m) {
#pragma unroll
        for (int off = 16; off > 0; off >>= 1) {
            tw[m] += __shfl_xor_sync(0xffffffffu, tw[m], off);
            tu[m] += __shfl_xor_sync(0xffffffffu, tu[m], off);
        }
    }
    if (lane == 0) {
        float* ow = gwp + ((size_t)grp * BB + b) * MM;
        float* ou = gup + ((size_t)grp * BB + b) * MM;
#pragma unroll
        for (int m = 0; m < 4; ++m) {
            ow[wrp + 8 * m] = tw[m];
            ou[wrp + 8 * m] = tu[m];
        }
    }
}

// ---------------- K2: reduce partials + full scalar solve ----------------
__global__ __launch_bounds__(256)
void k2_solve(void) {
    __shared__ float sE[MM * MM];
    __shared__ float sF[MM * MM];

    const int b   = blockIdx.x;
    const int tid = threadIdx.x;

    {
        float4 aE = make_float4(0.f, 0.f, 0.f, 0.f);
        float4 aF = aE;
#pragma unroll
        for (int g = 0; g < NG; ++g) {
            const size_t base4 = ((size_t)g * BB + b) * (MM * MM / 4) + tid;
            float4 e = ((const float4*)gEp)[base4];
            float4 f = ((const float4*)gFp)[base4];
            aE.x += e.x; aE.y += e.y; aE.z += e.z; aE.w += e.w;
            aF.x += f.x; aF.y += f.y; aF.z += f.z; aF.w += f.w;
        }
        ((float4*)sE)[tid] = aE;
        ((float4*)sF)[tid] = aF;
    }
    __syncthreads();

    if (tid >= 32) return;
    const int j = tid;

    float w_own = 0.f, u_own = 0.f;
#pragma unroll
    for (int g = 0; g < NG; ++g) {
        w_own += gwp[((size_t)g * BB + b) * MM + j];
        u_own += gup[((size_t)g * BB + b) * MM + j];
    }

    // backward solve for a (thread j holds E column j)
    float ecol[MM];
#pragma unroll
    for (int i = 0; i < MM; ++i) ecol[i] = sE[i * MM + j];
    float a_own = 0.0f, r_own = 0.0f;
#pragma unroll
    for (int ii = 0; ii < MM; ++ii) {
        const int i = MM - 1 - ii;
        float contrib = (j > i) ? a_own * ecol[i] : 0.0f;
#pragma unroll
        for (int off = 16; off > 0; off >>= 1)
            contrib += __shfl_xor_sync(0xffffffffu, contrib, off);
        const float ediag = __shfl_sync(0xffffffffu, ecol[i], i);
        const float wi    = __shfl_sync(0xffffffffu, w_own, i);
        const float ai    = (-wi - contrib) / ediag;
        if (j == i) { a_own = ai; r_own = 1.0f / ediag; }
    }

    const float g = sE[(MM - 1) * MM + (MM - 1)] / sF[(MM - 1) * MM + (MM - 1)];

    // v_j = -u_j - sum_i a_i F[j][i]
    float v_own = -u_own;
#pragma unroll
    for (int q = 0; q < 8; ++q) {
        float4 fv = *(const float4*)&sF[j * MM + q * 4];
        v_own -= __shfl_sync(0xffffffffu, a_own, q * 4 + 0) * fv.x;
        v_own -= __shfl_sync(0xffffffffu, a_own, q * 4 + 1) * fv.y;
        v_own -= __shfl_sync(0xffffffffu, a_own, q * 4 + 2) * fv.z;
        v_own -= __shfl_sync(0xffffffffu, a_own, q * 4 + 3) * fv.w;
    }

    // forward solve for c (thread j holds E row j)
    float erow[MM];
#pragma unroll
    for (int q = 0; q < 8; ++q) {
        float4 v = *(const float4*)&sE[j * MM + q * 4];
        erow[q * 4 + 0] = v.x; erow[q * 4 + 1] = v.y;
        erow[q * 4 + 2] = v.z; erow[q * 4 + 3] = v.w;
    }
    float c_own = 0.0f;
#pragma unroll
    for (int i = 0; i < MM; ++i) {
        float contrib = (j < i) ? c_own * erow[i] : 0.0f;
#pragma unroll
        for (int off = 16; off > 0; off >>= 1)
            contrib += __shfl_xor_sync(0xffffffffu, contrib, off);
        const float ri = __shfl_sync(0xffffffffu, r_own, i);
        const float ai = __shfl_sync(0xffffffffu, a_own, i);
        const float vi = __shfl_sync(0xffffffffu, v_own, i);
        const float ci = ai - ri * (g * vi + contrib);
        if (j == i) c_own = ci;
    }

    gya[b * MM + j] = g * a_own;
    gcc[b * MM + j] = c_own;
    if (j == 0) gg[b] = g;
}

// ---------------- K3: out = g frc + sum (g a_j) y_j - sum c_i s_i --------
__global__ __launch_bounds__(256)
void k3_out(const float* __restrict__ S, const float* __restrict__ Y,
            const float* __restrict__ FRC, float* __restrict__ OUT) {
    __shared__ float sya[MM];
    __shared__ float scc[MM];
    __shared__ float sg[1];

    const int b  = blockIdx.x >> 3;
    const int ch = blockIdx.x & 7;
    const int tid = threadIdx.x;

    if (tid < MM) { sya[tid] = gya[b * MM + tid]; scc[tid] = gcc[b * MM + tid]; }
    if (tid == MM) sg[0] = gg[b];
    __syncthreads();

    const size_t d0 = (size_t)ch * CH3 + tid * 4;
    const float g = sg[0];
    float4 f = *(const float4*)(FRC + (size_t)b * DD + d0);
    u64 acc0 = pk2(g * f.x, g * f.y);
    u64 acc1 = pk2(g * f.z, g * f.w);

#pragma unroll
    for (int j = 0; j < MM; ++j) {
        ulonglong2 yv = *(const ulonglong2*)(Y + ((size_t)j * BB + b) * DD + d0);
        const float cv = sya[j];
        const u64 cc = pk2(cv, cv);
        acc0 = fma2(cc, yv.x, acc0);
        acc1 = fma2(cc, yv.y, acc1);
    }
#pragma unroll
    for (int i = 0; i < MM; ++i) {
        ulonglong2 sv = *(const ulonglong2*)(S + ((size_t)i * BB + b) * DD + d0);
        const float cv = -scc[i];
        const u64 cc = pk2(cv, cv);
        acc0 = fma2(cc, sv.x, acc0);
        acc1 = fma2(cc, sv.y, acc1);
    }

    float2 o0 = upk2(acc0), o1 = upk2(acc1);
    float4 o; o.x = o0.x; o.y = o0.y; o.z = o1.x; o.w = o1.y;
    *(float4*)(OUT + (size_t)b * DD + d0) = o;
}

// ---------------- launch ----------------
extern "C" void kernel_launch(void* const* d_in, const int* in_sizes, int n_in,
                              void* d_out, int out_size) {
    const float* S   = (const float*)d_in[0];  // (M, B, D)
    const float* Y   = (const float*)d_in[1];  // (M, B, D)
    const float* FRC = (const float*)d_in[2];  // (B, D)
    float* OUT = (float*)d_out;                // (B, D)

    static bool attr_set = false;
    if (!attr_set) {
        cudaFuncSetAttribute(k1_gram,
                             cudaFuncAttributeMaxDynamicSharedMemorySize,
                             K1_SMEM);
        attr_set = true;
    }

    k1_gram<<<BB * NG, 256, K1_SMEM>>>(S, Y, FRC);
    k2_solve<<<BB, 256>>>();
    k3_out<<<BB * NCH3, 256>>>(S, Y, FRC, OUT);
}

// round 14
// speedup vs baseline: 1.6737x; 1.6703x over previous
#include <cuda_runtime.h>
#include <cstdint>

// LBFGS via Gram reformulation; K1 computes ONLY the 36 upper 4x4 tiles of
// E=S.Y^T and F=Y.Y^T (solves never read lower-E; F symmetric, mirrored in K2).
// 160 threads: 144 workers = 36 tiles x 4 K-quarters (4.5 active warps).
// Cross-dq reduce via shfl within 4-lane groups, direct STG (no smem scratch).

#define MM 32
#define BB 64
#define DD 8192
#define NG 8
#define KG (DD / NG)
#define SUB 256
#define NSUB (KG / SUB)
#define ST 260
#define NT1 160
#define K1_SMEM ((64 * ST + SUB) * 4)   // 67584 B
#define CH3 1024
#define NCH3 (DD / CH3)

typedef unsigned long long u64;

__device__ float gEp[NG * BB * MM * MM];
__device__ float gFp[NG * BB * MM * MM];
__device__ float gwp[NG * BB * MM];
__device__ float gup[NG * BB * MM];
__device__ float gya[BB * MM];
__device__ float gcc[BB * MM];
__device__ float gg[BB];

__device__ __forceinline__ u64 pk2(float a, float b) {
    u64 r; asm("mov.b64 %0, {%1,%2};" : "=l"(r) : "f"(a), "f"(b)); return r;
}
__device__ __forceinline__ float2 upk2(u64 v) {
    float2 f; asm("mov.b64 {%0,%1}, %2;" : "=f"(f.x), "=f"(f.y) : "l"(v)); return f;
}
__device__ __forceinline__ u64 fma2(u64 a, u64 b, u64 c) {
    u64 d; asm("fma.rn.f32x2 %0, %1, %2, %3;" : "=l"(d) : "l"(a), "l"(b), "l"(c)); return d;
}
__device__ __forceinline__ float dot4(float4 a, float4 b) {
    return a.x * b.x + a.y * b.y + a.z * b.z + a.w * b.w;
}

__global__ __launch_bounds__(NT1, 3)
void k1_gram(const float* __restrict__ S, const float* __restrict__ Y,
             const float* __restrict__ FRC) {
    extern __shared__ __align__(16) float smem[];
    float* sS  = smem;
    float* sY  = smem + 32 * ST;
    float* sFr = smem + 64 * ST;

    const int b   = blockIdx.x >> 3;
    const int grp = blockIdx.x & 7;
    const int tid = threadIdx.x;
    const int wrp = tid >> 5;
    const int lane = tid & 31;
    const bool work = tid < 144;
    const int a  = work ? (tid >> 2) : 0;
    const int dq = tid & 3;
    int ti = 0, rem = a;
    while (rem >= 8 - ti) { rem -= 8 - ti; ++ti; }
    const int tj = ti + rem;
    const int rA = 4 * ti, rB = 4 * tj;

    u64 accE[16], accF[16];
#pragma unroll
    for (int n = 0; n < 16; ++n) { accE[n] = 0ull; accF[n] = 0ull; }
    float tw[7], tu[7];
#pragma unroll
    for (int m = 0; m < 7; ++m) { tw[m] = 0.f; tu[m] = 0.f; }

#pragma unroll 1
    for (int sub = 0; sub < NSUB; ++sub) {
        const size_t cb = (size_t)grp * KG + (size_t)sub * SUB;
        for (int i = tid; i < 2048; i += NT1) {
            const int row = i >> 6;
            const int c4  = (i & 63) * 4;
            const size_t g = ((size_t)row * BB + b) * DD + cb + c4;
            *(float4*)&sS[row * ST + c4] = *(const float4*)(S + g);
            *(float4*)&sY[row * ST + c4] = *(const float4*)(Y + g);
        }
        if (tid < 64)
            *(float4*)&sFr[tid * 4] =
                *(const float4*)(FRC + (size_t)b * DD + cb + tid * 4);
        __syncthreads();

        if (work) {
#pragma unroll
            for (int d4 = 0; d4 < 16; ++d4) {
                const int c = dq * 64 + ((d4 * 4 + dq * 8) & 63);
                ulonglong2 su[4], zu[4], yu[4];
#pragma unroll
                for (int k = 0; k < 4; ++k) {
                    su[k] = *(const ulonglong2*)&sS[(rA + k) * ST + c];
                    zu[k] = *(const ulonglong2*)&sY[(rA + k) * ST + c];
                }
#pragma unroll
                for (int l = 0; l < 4; ++l)
                    yu[l] = *(const ulonglong2*)&sY[(rB + l) * ST + c];
#pragma unroll
                for (int k = 0; k < 4; ++k)
#pragma unroll
                    for (int l = 0; l < 4; ++l) {
                        accE[k * 4 + l] = fma2(su[k].x, yu[l].x, accE[k * 4 + l]);
                        accE[k * 4 + l] = fma2(su[k].y, yu[l].y, accE[k * 4 + l]);
                        accF[k * 4 + l] = fma2(zu[k].x, yu[l].x, accF[k * 4 + l]);
                        accF[k * 4 + l] = fma2(zu[k].y, yu[l].y, accF[k * 4 + l]);
                    }
            }
        }

        // w/u partial dots: warp wrp handles rows wrp, wrp+5, ...
#pragma unroll
        for (int m = 0; m < 7; ++m) {
            const int r = wrp + 5 * m;
            if (r < 32) {
                float4 a0 = *(const float4*)&sS[r * ST + lane * 8];
                float4 a1 = *(const float4*)&sS[r * ST + lane * 8 + 4];
                float4 b0 = *(const float4*)&sY[r * ST + lane * 8];
                float4 b1 = *(const float4*)&sY[r * ST + lane * 8 + 4];
                float4 f0 = *(const float4*)&sFr[lane * 8];
                float4 f1 = *(const float4*)&sFr[lane * 8 + 4];
                tw[m] += dot4(a0, f0) + dot4(a1, f1);
                tu[m] += dot4(b0, f0) + dot4(b1, f1);
            }
        }
        __syncthreads();
    }

    // cross-dq reduce (4-lane groups) + direct STG of the 36 upper tiles
    float* outE = gEp + ((size_t)grp * BB + b) * (MM * MM);
    float* outF = gFp + ((size_t)grp * BB + b) * (MM * MM);
#pragma unroll
    for (int n = 0; n < 16; ++n) {
        float2 p = upk2(accE[n]);
        float e = p.x + p.y;
        e += __shfl_xor_sync(0xffffffffu, e, 1);
        e += __shfl_xor_sync(0xffffffffu, e, 2);
        float2 q = upk2(accF[n]);
        float f = q.x + q.y;
        f += __shfl_xor_sync(0xffffffffu, f, 1);
        f += __shfl_xor_sync(0xffffffffu, f, 2);
        if (work && dq == 0) {
            const int idx = (rA + (n >> 2)) * MM + rB + (n & 3);
            outE[idx] = e;
            outF[idx] = f;
        }
    }

    // w/u: shfl-reduce, lane0 writes rows wrp, wrp+5, ...
#pragma unroll
    for (int m = 0; m < 7; ++m) {
#pragma unroll
        for (int off = 16; off > 0; off >>= 1) {
            tw[m] += __shfl_xor_sync(0xffffffffu, tw[m], off);
            tu[m] += __shfl_xor_sync(0xffffffffu, tu[m], off);
        }
    }
    if (lane == 0) {
        float* ow = gwp + ((size_t)grp * BB + b) * MM;
        float* ou = gup + ((size_t)grp * BB + b) * MM;
#pragma unroll
        for (int m = 0; m < 7; ++m) {
            const int r = wrp + 5 * m;
            if (r < 32) { ow[r] = tw[m]; ou[r] = tu[m]; }
        }
    }
}

__global__ __launch_bounds__(256)
void k2_solve(void) {
    __shared__ float sE[MM * MM];
    __shared__ float sF[MM * MM];
    const int b   = blockIdx.x;
    const int tid = threadIdx.x;

#pragma unroll
    for (int e = 0; e < 4; ++e) {
        const int el = tid + e * 256;
        const int I = el >> 5, J = el & 31;
        const int ii = (I <= J) ? I : J;
        const int jj = (I <= J) ? J : I;
        float aE = 0.f, aF = 0.f;
#pragma unroll
        for (int g = 0; g < NG; ++g) {
            const float* Eb = gEp + ((size_t)g * BB + b) * (MM * MM);
            const float* Fb = gFp + ((size_t)g * BB + b) * (MM * MM);
            if (I <= J) aE += Eb[I * MM + J];
            aF += Fb[ii * MM + jj];      // mirror: F symmetric
        }
        sE[el] = aE;
        sF[el] = aF;
    }
    __syncthreads();

    if (tid >= 32) return;
    const int j = tid;

    float w_own = 0.f, u_own = 0.f;
#pragma unroll
    for (int g = 0; g < NG; ++g) {
        w_own += gwp[((size_t)g * BB + b) * MM + j];
        u_own += gup[((size_t)g * BB + b) * MM + j];
    }

    float ecol[MM];
#pragma unroll
    for (int i = 0; i < MM; ++i) ecol[i] = sE[i * MM + j];
    float a_own = 0.0f, r_own = 0.0f;
#pragma unroll
    for (int ii2 = 0; ii2 < MM; ++ii2) {
        const int i = MM - 1 - ii2;
        float contrib = (j > i) ? a_own * ecol[i] : 0.0f;
#pragma unroll
        for (int off = 16; off > 0; off >>= 1)
            contrib += __shfl_xor_sync(0xffffffffu, contrib, off);
        const float ediag = __shfl_sync(0xffffffffu, ecol[i], i);
        const float wi    = __shfl_sync(0xffffffffu, w_own, i);
        const float ai    = (-wi - contrib) / ediag;
        if (j == i) { a_own = ai; r_own = 1.0f / ediag; }
    }

    const float g = sE[(MM - 1) * MM + (MM - 1)] / sF[(MM - 1) * MM + (MM - 1)];

    float v_own = -u_own;
#pragma unroll
    for (int q = 0; q < 8; ++q) {
        float4 fv = *(const float4*)&sF[j * MM + q * 4];
        v_own -= __shfl_sync(0xffffffffu, a_own, q * 4 + 0) * fv.x;
        v_own -= __shfl_sync(0xffffffffu, a_own, q * 4 + 1) * fv.y;
        v_own -= __shfl_sync(0xffffffffu, a_own, q * 4 + 2) * fv.z;
        v_own -= __shfl_sync(0xffffffffu, a_own, q * 4 + 3) * fv.w;
    }

    float erow[MM];
#pragma unroll
    for (int q = 0; q < 8; ++q) {
        float4 v = *(const float4*)&sE[j * MM + q * 4];
        erow[q * 4 + 0] = v.x; erow[q * 4 + 1] = v.y;
        erow[q * 4 + 2] = v.z; erow[q * 4 + 3] = v.w;
    }
    float c_own = 0.0f;
#pragma unroll
    for (int i = 0; i < MM; ++i) {
        float contrib = (j < i) ? c_own * erow[i] : 0.0f;
#pragma unroll
        for (int off = 16; off > 0; off >>= 1)
            contrib += __shfl_xor_sync(0xffffffffu, contrib, off);
        const float ri = __shfl_sync(0xffffffffu, r_own, i);
        const float ai = __shfl_sync(0xffffffffu, a_own, i);
        const float vi = __shfl_sync(0xffffffffu, v_own, i);
        const float ci = ai - ri * (g * vi + contrib);
        if (j == i) c_own = ci;
    }

    gya[b * MM + j] = g * a_own;
    gcc[b * MM + j] = c_own;
    if (j == 0) gg[b] = g;
}

__global__ __launch_bounds__(256)
void k3_out(const float* __restrict__ S, const float* __restrict__ Y,
            const float* __restrict__ FRC, float* __restrict__ OUT) {
    __shared__ float sya[MM];
    __shared__ float scc[MM];
    __shared__ float sg[1];
    const int b  = blockIdx.x >> 3;
    const int ch = blockIdx.x & 7;
    const int tid = threadIdx.x;

    if (tid < MM) { sya[tid] = gya[b * MM + tid]; scc[tid] = gcc[b * MM + tid]; }
    if (tid == MM) sg[0] = gg[b];
    __syncthreads();

    const size_t d0 = (size_t)ch * CH3 + tid * 4;
    const float g = sg[0];
    float4 f = *(const float4*)(FRC + (size_t)b * DD + d0);
    u64 acc0 = pk2(g * f.x, g * f.y);
    u64 acc1 = pk2(g * f.z, g * f.w);

#pragma unroll
    for (int j = 0; j < MM; ++j) {
        ulonglong2 yv = *(const ulonglong2*)(Y + ((size_t)j * BB + b) * DD + d0);
        const float cv = sya[j];
        const u64 cc = pk2(cv, cv);
        acc0 = fma2(cc, yv.x, acc0);
        acc1 = fma2(cc, yv.y, acc1);
    }
#pragma unroll
    for (int i = 0; i < MM; ++i) {
        ulonglong2 sv = *(const ulonglong2*)(S + ((size_t)i * BB + b) * DD + d0);
        const float cv = -scc[i];
        const u64 cc = pk2(cv, cv);
        acc0 = fma2(cc, sv.x, acc0);
        acc1 = fma2(cc, sv.y, acc1);
    }

    float2 o0 = upk2(acc0), o1 = upk2(acc1);
    float4 o; o.x = o0.x; o.y = o0.y; o.z = o1.x; o.w = o1.y;
    *(float4*)(OUT + (size_t)b * DD + d0) = o;
}

extern "C" void kernel_launch(void* const* d_in, const int* in_sizes, int n_in,
                              void* d_out, int out_size) {
    const float* S   = (const float*)d_in[0];
    const float* Y   = (const float*)d_in[1];
    const float* FRC = (const float*)d_in[2];
    float* OUT = (float*)d_out;

    static bool attr_set = false;
    if (!attr_set) {
        cudaFuncSetAttribute(k1_gram,
                             cudaFuncAttributeMaxDynamicSharedMemorySize,
                             K1_SMEM);
        attr_set = true;
    }

    k1_gram<<<BB * NG, NT1, K1_SMEM>>>(S, Y, FRC);
    k2_solve<<<BB, 256>>>();
    k3_out<<<BB * NCH3, 256>>>(S, Y, FRC, OUT);
}

// round 15
// speedup vs baseline: 2.2604x; 1.3506x over previous
#include <cuda_runtime.h>
#include <cstdint>

// LBFGS via Gram reformulation; Gram via mma.sync tf32 (generic PTX, sm_80+).
// K1: D[64x32] = [S;Y] . Y^T per (b,kgroup) using split-tf32 (hi/lo, 3 terms).
//     8 warps = 2 row-halves x 4-way k-split; partials STG'd per k-split.
// K2: sum 16 partials -> E,F; warp triangular solves -> g*a, c, g.
// K3: out = g*frc + sum (g a_j) y_j - sum c_i s_i.

#define MM 32
#define BB 64
#define DD 8192
#define NKG 4
#define KSL (DD / NKG)        // 2048
#define KC 64
#define NCH (KSL / KC)        // 32
#define ST 68                 // slab row stride (floats)
#define SLAB (64 * ST)        // one hi or lo slab
#define BUFF (2 * SLAB)       // hi + lo
#define K1_SMEM (2 * BUFF * 4)  // 69632 B
#define CH3 1024
#define NCH3 (DD / CH3)

typedef unsigned long long u64;

__device__ float gGp[NKG * BB * 4 * 64 * 32];   // [kg][b][ksplit][row64][col32]
__device__ float gwp[NKG * BB * MM];
__device__ float gup[NKG * BB * MM];
__device__ float gya[BB * MM];
__device__ float gcc[BB * MM];
__device__ float gg[BB];

__device__ __forceinline__ u64 pk2(float a, float b) {
    u64 r; asm("mov.b64 %0, {%1,%2};" : "=l"(r) : "f"(a), "f"(b)); return r;
}
__device__ __forceinline__ float2 upk2(u64 v) {
    float2 f; asm("mov.b64 {%0,%1}, %2;" : "=f"(f.x), "=f"(f.y) : "l"(v)); return f;
}
__device__ __forceinline__ u64 fma2(u64 a, u64 b, u64 c) {
    u64 d; asm("fma.rn.f32x2 %0, %1, %2, %3;" : "=l"(d) : "l"(a), "l"(b), "l"(c)); return d;
}
__device__ __forceinline__ float dot4(float4 a, float4 b) {
    return a.x * b.x + a.y * b.y + a.z * b.z + a.w * b.w;
}
__device__ __forceinline__ uint32_t tf32c(float x) {
    uint32_t r; asm("cvt.rna.tf32.f32 %0, %1;" : "=r"(r) : "f"(x)); return r;
}

#define MMA(c, A, B) \
    asm volatile("mma.sync.aligned.m16n8k8.row.col.f32.tf32.tf32.f32 " \
        "{%0,%1,%2,%3},{%4,%5,%6,%7},{%8,%9},{%0,%1,%2,%3};" \
        : "+f"((c)[0]), "+f"((c)[1]), "+f"((c)[2]), "+f"((c)[3]) \
        : "r"((A)[0]), "r"((A)[1]), "r"((A)[2]), "r"((A)[3]), \
          "r"((B)[0]), "r"((B)[1]))

__global__ __launch_bounds__(256, 2)
void k1_gram(const float* __restrict__ S, const float* __restrict__ Y,
             const float* __restrict__ FRC) {
    extern __shared__ __align__(16) uint32_t smem[];   // 2 bufs x (hi|lo) slabs

    const int b   = blockIdx.x >> 2;
    const int kg  = blockIdx.x & 3;
    const int tid = threadIdx.x;
    const int w   = tid >> 5;
    const int lane = tid & 31;
    const int g = lane >> 2, q = lane & 3;
    const int ms = (w & 1) * 2;      // mt pair {ms, ms+1} -> rows ms*16..+31
    const int ks = w >> 1;           // k-split 0..3

    // loader role
    const int r  = tid >> 3;                 // 0..31
    const int cb = (tid & 7) * 8;            // 0..56
    const size_t gS = ((size_t)r * BB + b) * DD + (size_t)kg * KSL + cb;
    const size_t gF = (size_t)b * DD + (size_t)kg * KSL + cb;

    float acc[2][4][4];
#pragma unroll
    for (int m = 0; m < 2; ++m)
#pragma unroll
        for (int n = 0; n < 4; ++n)
#pragma unroll
            for (int e = 0; e < 4; ++e) acc[m][n][e] = 0.0f;
    float tw = 0.f, tu = 0.f;

    float4 s0, s1, y0, y1, f0, f1;
    auto ldregs = [&](int c) {
        const size_t o = gS + (size_t)c * KC;
        s0 = *(const float4*)(S + o);     s1 = *(const float4*)(S + o + 4);
        y0 = *(const float4*)(Y + o);     y1 = *(const float4*)(Y + o + 4);
        const size_t of = gF + (size_t)c * KC;
        f0 = *(const float4*)(FRC + of);  f1 = *(const float4*)(FRC + of + 4);
    };
    auto split8 = [&](float4 a, float4 b2, uint32_t* hi, uint32_t* lo) {
        const float v[8] = {a.x, a.y, a.z, a.w, b2.x, b2.y, b2.z, b2.w};
#pragma unroll
        for (int e = 0; e < 8; ++e) {
            hi[e] = tf32c(v[e]);
            lo[e] = tf32c(v[e] - __uint_as_float(hi[e]));
        }
    };
    auto store = [&](int c) {
        uint32_t* buf = smem + (c & 1) * BUFF;
        uint32_t hi[8], lo[8];
        split8(s0, s1, hi, lo);
        *(uint4*)&buf[r * ST + cb]            = *(uint4*)hi;
        *(uint4*)&buf[r * ST + cb + 4]        = *(uint4*)(hi + 4);
        *(uint4*)&buf[SLAB + r * ST + cb]     = *(uint4*)lo;
        *(uint4*)&buf[SLAB + r * ST + cb + 4] = *(uint4*)(lo + 4);
        split8(y0, y1, hi, lo);
        const int ry = 32 + r;
        *(uint4*)&buf[ry * ST + cb]            = *(uint4*)hi;
        *(uint4*)&buf[ry * ST + cb + 4]        = *(uint4*)(hi + 4);
        *(uint4*)&buf[SLAB + ry * ST + cb]     = *(uint4*)lo;
        *(uint4*)&buf[SLAB + ry * ST + cb + 4] = *(uint4*)(lo + 4);
        tw += dot4(s0, f0) + dot4(s1, f1);
        tu += dot4(y0, f0) + dot4(y1, f1);
    };

    ldregs(0); store(0); __syncthreads();

#pragma unroll 1
    for (int c = 0; c < NCH; ++c) {
        if (c + 1 < NCH) ldregs(c + 1);

        const uint32_t* bh = smem + (c & 1) * BUFF;
        const uint32_t* bl = bh + SLAB;
#pragma unroll
        for (int s2 = 0; s2 < 2; ++s2) {
            const int kb = (ks + s2 * 4) * 8;
            uint32_t Ah[2][4], Al[2][4], Bh[4][2], Bl[4][2];
#pragma unroll
            for (int m = 0; m < 2; ++m) {
                const int ia = ((ms + m) * 16 + g) * ST + kb + q;
                Ah[m][0] = bh[ia];          Ah[m][1] = bh[ia + 8 * ST];
                Ah[m][2] = bh[ia + 4];      Ah[m][3] = bh[ia + 8 * ST + 4];
                Al[m][0] = bl[ia];          Al[m][1] = bl[ia + 8 * ST];
                Al[m][2] = bl[ia + 4];      Al[m][3] = bl[ia + 8 * ST + 4];
            }
#pragma unroll
            for (int n = 0; n < 4; ++n) {
                const int ib = (32 + n * 8 + g) * ST + kb + q;
                Bh[n][0] = bh[ib];  Bh[n][1] = bh[ib + 4];
                Bl[n][0] = bl[ib];  Bl[n][1] = bl[ib + 4];
            }
#pragma unroll
            for (int m = 0; m < 2; ++m)
#pragma unroll
                for (int n = 0; n < 4; ++n) {
                    MMA(acc[m][n], Ah[m], Bh[n]);
                    MMA(acc[m][n], Ah[m], Bl[n]);
                    MMA(acc[m][n], Al[m], Bh[n]);
                }
        }

        if (c + 1 < NCH) store(c + 1);
        __syncthreads();
    }

    // writeback partials (per k-split; no cross-warp reduction needed)
    float* out = gGp + (((size_t)kg * BB + b) * 4 + ks) * (64 * 32);
#pragma unroll
    for (int m = 0; m < 2; ++m) {
        const int R = (ms + m) * 16 + g;
#pragma unroll
        for (int n = 0; n < 4; ++n) {
            const int C = n * 8 + 2 * q;
            *(float2*)&out[R * 32 + C]       = make_float2(acc[m][n][0], acc[m][n][1]);
            *(float2*)&out[(R + 8) * 32 + C] = make_float2(acc[m][n][2], acc[m][n][3]);
        }
    }

    // w/u: reduce over the 8 lanes sharing row r
#pragma unroll
    for (int off = 4; off > 0; off >>= 1) {
        tw += __shfl_xor_sync(0xffffffffu, tw, off);
        tu += __shfl_xor_sync(0xffffffffu, tu, off);
    }
    if ((lane & 7) == 0) {
        gwp[((size_t)kg * BB + b) * MM + r] = tw;
        gup[((size_t)kg * BB + b) * MM + r] = tu;
    }
}

__global__ __launch_bounds__(256)
void k2_solve(void) {
    __shared__ float sE[MM * MM];
    __shared__ float sF[MM * MM];
    const int b = blockIdx.x;
    const int tid = threadIdx.x;

#pragma unroll
    for (int e = 0; e < 4; ++e) {
        const int el = tid + e * 256;
        const int I = el >> 5, J = el & 31;
        float aE = 0.f, aF = 0.f;
#pragma unroll
        for (int p = 0; p < NKG * 4; ++p) {
            const int kg2 = p >> 2, ksp = p & 3;
            const float* Gb = gGp + (((size_t)kg2 * BB + b) * 4 + ksp) * (64 * 32);
            aE += Gb[I * 32 + J];
            aF += Gb[(32 + I) * 32 + J];
        }
        sE[el] = aE;
        sF[el] = aF;
    }
    __syncthreads();

    if (tid >= 32) return;
    const int j = tid;

    float w_own = 0.f, u_own = 0.f;
#pragma unroll
    for (int g = 0; g < NKG; ++g) {
        w_own += gwp[((size_t)g * BB + b) * MM + j];
        u_own += gup[((size_t)g * BB + b) * MM + j];
    }

    float ecol[MM];
#pragma unroll
    for (int i = 0; i < MM; ++i) ecol[i] = sE[i * MM + j];
    float a_own = 0.0f, r_own = 0.0f;
#pragma unroll
    for (int ii = 0; ii < MM; ++ii) {
        const int i = MM - 1 - ii;
        float contrib = (j > i) ? a_own * ecol[i] : 0.0f;
#pragma unroll
        for (int off = 16; off > 0; off >>= 1)
            contrib += __shfl_xor_sync(0xffffffffu, contrib, off);
        const float ediag = __shfl_sync(0xffffffffu, ecol[i], i);
        const float wi    = __shfl_sync(0xffffffffu, w_own, i);
        const float ai    = (-wi - contrib) / ediag;
        if (j == i) { a_own = ai; r_own = 1.0f / ediag; }
    }

    const float g = sE[(MM - 1) * MM + (MM - 1)] / sF[(MM - 1) * MM + (MM - 1)];

    float v_own = -u_own;
#pragma unroll
    for (int qq = 0; qq < 8; ++qq) {
        float4 fv = *(const float4*)&sF[j * MM + qq * 4];
        v_own -= __shfl_sync(0xffffffffu, a_own, qq * 4 + 0) * fv.x;
        v_own -= __shfl_sync(0xffffffffu, a_own, qq * 4 + 1) * fv.y;
        v_own -= __shfl_sync(0xffffffffu, a_own, qq * 4 + 2) * fv.z;
        v_own -= __shfl_sync(0xffffffffu, a_own, qq * 4 + 3) * fv.w;
    }

    float erow[MM];
#pragma unroll
    for (int qq = 0; qq < 8; ++qq) {
        float4 v = *(const float4*)&sE[j * MM + qq * 4];
        erow[qq * 4 + 0] = v.x; erow[qq * 4 + 1] = v.y;
        erow[qq * 4 + 2] = v.z; erow[qq * 4 + 3] = v.w;
    }
    float c_own = 0.0f;
#pragma unroll
    for (int i = 0; i < MM; ++i) {
        float contrib = (j < i) ? c_own * erow[i] : 0.0f;
#pragma unroll
        for (int off = 16; off > 0; off >>= 1)
            contrib += __shfl_xor_sync(0xffffffffu, contrib, off);
        const float ri = __shfl_sync(0xffffffffu, r_own, i);
        const float ai = __shfl_sync(0xffffffffu, a_own, i);
        const float vi = __shfl_sync(0xffffffffu, v_own, i);
        const float ci = ai - ri * (g * vi + contrib);
        if (j == i) c_own = ci;
    }

    gya[b * MM + j] = g * a_own;
    gcc[b * MM + j] = c_own;
    if (j == 0) gg[b] = g;
}

__global__ __launch_bounds__(256)
void k3_out(const float* __restrict__ S, const float* __restrict__ Y,
            const float* __restrict__ FRC, float* __restrict__ OUT) {
    __shared__ float sya[MM];
    __shared__ float scc[MM];
    __shared__ float sg[1];
    const int b  = blockIdx.x >> 3;
    const int ch = blockIdx.x & 7;
    const int tid = threadIdx.x;

    if (tid < MM) { sya[tid] = gya[b * MM + tid]; scc[tid] = gcc[b * MM + tid]; }
    if (tid == MM) sg[0] = gg[b];
    __syncthreads();

    const size_t d0 = (size_t)ch * CH3 + tid * 4;
    const float g = sg[0];
    float4 f = *(const float4*)(FRC + (size_t)b * DD + d0);
    u64 acc0 = pk2(g * f.x, g * f.y);
    u64 acc1 = pk2(g * f.z, g * f.w);

#pragma unroll
    for (int j = 0; j < MM; ++j) {
        ulonglong2 yv = *(const ulonglong2*)(Y + ((size_t)j * BB + b) * DD + d0);
        const float cv = sya[j];
        const u64 cc = pk2(cv, cv);
        acc0 = fma2(cc, yv.x, acc0);
        acc1 = fma2(cc, yv.y, acc1);
    }
#pragma unroll
    for (int i = 0; i < MM; ++i) {
        ulonglong2 sv = *(const ulonglong2*)(S + ((size_t)i * BB + b) * DD + d0);
        const float cv = -scc[i];
        const u64 cc = pk2(cv, cv);
        acc0 = fma2(cc, sv.x, acc0);
        acc1 = fma2(cc, sv.y, acc1);
    }

    float2 o0 = upk2(acc0), o1 = upk2(acc1);
    float4 o; o.x = o0.x; o.y = o0.y; o.z = o1.x; o.w = o1.y;
    *(float4*)(OUT + (size_t)b * DD + d0) = o;
}

extern "C" void kernel_launch(void* const* d_in, const int* in_sizes, int n_in,
                              void* d_out, int out_size) {
    const float* S   = (const float*)d_in[0];
    const float* Y   = (const float*)d_in[1];
    const float* FRC = (const float*)d_in[2];
    float* OUT = (float*)d_out;

    static bool attr_set = false;
    if (!attr_set) {
        cudaFuncSetAttribute(k1_gram,
                             cudaFuncAttributeMaxDynamicSharedMemorySize,
                             K1_SMEM);
        attr_set = true;
    }

    k1_gram<<<BB * NKG, 256, K1_SMEM>>>(S, Y, FRC);
    k2_solve<<<BB, 256>>>();
    k3_out<<<BB * NCH3, 256>>>(S, Y, FRC, OUT);
}

// round 16
// speedup vs baseline: 2.4282x; 1.0742x over previous
#include <cuda_runtime.h>
#include <cstdint>

// LBFGS via Gram reformulation; Gram via mma.sync tf32 + ldmatrix fragments.
// K1: D[64x32] = [S;Y].Y^T per (b,kgroup), split-tf32 (hi/lo, 3 MMA terms).
//     8 warps = 2 row-halves x 4-way k-split. Fragments loaded with
//     ldmatrix.x4 (16 per warp-chunk instead of 64 scalar LDS).
// K2: sum 16 partials -> E,F; warp triangular solves. K3: linear combine.

#define MM 32
#define BB 64
#define DD 8192
#define NKG 4
#define KSL (DD / NKG)
#define KC 64
#define NCH (KSL / KC)
#define ST 68
#define SLAB (64 * ST)
#define BUFF (2 * SLAB)
#define K1_SMEM (2 * BUFF * 4)
#define CH3 1024
#define NCH3 (DD / CH3)

typedef unsigned long long u64;

__device__ float gGp[NKG * BB * 4 * 64 * 32];
__device__ float gwp[NKG * BB * MM];
__device__ float gup[NKG * BB * MM];
__device__ float gya[BB * MM];
__device__ float gcc[BB * MM];
__device__ float gg[BB];

__device__ __forceinline__ u64 pk2(float a, float b) {
    u64 r; asm("mov.b64 %0, {%1,%2};" : "=l"(r) : "f"(a), "f"(b)); return r;
}
__device__ __forceinline__ float2 upk2(u64 v) {
    float2 f; asm("mov.b64 {%0,%1}, %2;" : "=f"(f.x), "=f"(f.y) : "l"(v)); return f;
}
__device__ __forceinline__ u64 fma2(u64 a, u64 b, u64 c) {
    u64 d; asm("fma.rn.f32x2 %0, %1, %2, %3;" : "=l"(d) : "l"(a), "l"(b), "l"(c)); return d;
}
__device__ __forceinline__ float dot4(float4 a, float4 b) {
    return a.x * b.x + a.y * b.y + a.z * b.z + a.w * b.w;
}
__device__ __forceinline__ uint32_t tf32c(float x) {
    uint32_t r; asm("cvt.rna.tf32.f32 %0, %1;" : "=r"(r) : "f"(x)); return r;
}

#define LDMX4(R, addr) \
    asm volatile("ldmatrix.sync.aligned.m8n8.x4.shared.b16 {%0,%1,%2,%3},[%4];" \
        : "=r"((R)[0]), "=r"((R)[1]), "=r"((R)[2]), "=r"((R)[3]) : "r"(addr))

#define MMA(c, A, b0, b1) \
    asm volatile("mma.sync.aligned.m16n8k8.row.col.f32.tf32.tf32.f32 " \
        "{%0,%1,%2,%3},{%4,%5,%6,%7},{%8,%9},{%0,%1,%2,%3};" \
        : "+f"((c)[0]), "+f"((c)[1]), "+f"((c)[2]), "+f"((c)[3]) \
        : "r"((A)[0]), "r"((A)[1]), "r"((A)[2]), "r"((A)[3]), "r"(b0), "r"(b1))

__global__ __launch_bounds__(256, 2)
void k1_gram(const float* __restrict__ S, const float* __restrict__ Y,
             const float* __restrict__ FRC) {
    extern __shared__ __align__(16) uint32_t smem[];

    const int b    = blockIdx.x >> 2;
    const int kg   = blockIdx.x & 3;
    const int tid  = threadIdx.x;
    const int w    = tid >> 5;
    const int lane = tid & 31;
    const int ms   = (w & 1) * 2;
    const int ks   = w >> 1;

    // ldmatrix per-lane byte offsets (loop-invariant)
    const int mat = lane >> 3, rin = lane & 7;
    uint32_t offA[2], offB[2];
#pragma unroll
    for (int m = 0; m < 2; ++m)
        offA[m] = ((uint32_t)(((ms + m) * 16 + (mat & 1) * 8 + rin) * ST
                              + (mat >> 1) * 4)) * 4u;
#pragma unroll
    for (int p = 0; p < 2; ++p)
        offB[p] = ((uint32_t)((32 + (p * 2 + (mat >> 1)) * 8 + rin) * ST
                              + (mat & 1) * 4)) * 4u;
    const uint32_t sbase = (uint32_t)__cvta_generic_to_shared(smem);
    const uint32_t LOB = SLAB * 4;   // lo-slab byte offset

    // loader role
    const int r  = tid >> 3;
    const int cb = (tid & 7) * 8;
    const size_t gS = ((size_t)r * BB + b) * DD + (size_t)kg * KSL + cb;
    const size_t gF = (size_t)b * DD + (size_t)kg * KSL + cb;

    float acc[2][4][4];
#pragma unroll
    for (int m = 0; m < 2; ++m)
#pragma unroll
        for (int n = 0; n < 4; ++n)
#pragma unroll
            for (int e = 0; e < 4; ++e) acc[m][n][e] = 0.0f;
    float tw = 0.f, tu = 0.f;

    float4 s0, s1, y0, y1, f0, f1;
    auto ldregs = [&](int c) {
        const size_t o = gS + (size_t)c * KC;
        s0 = *(const float4*)(S + o);     s1 = *(const float4*)(S + o + 4);
        y0 = *(const float4*)(Y + o);     y1 = *(const float4*)(Y + o + 4);
        const size_t of = gF + (size_t)c * KC;
        f0 = *(const float4*)(FRC + of);  f1 = *(const float4*)(FRC + of + 4);
    };
    auto split8 = [&](float4 a, float4 b2, uint32_t* hi, uint32_t* lo) {
        const float v[8] = {a.x, a.y, a.z, a.w, b2.x, b2.y, b2.z, b2.w};
#pragma unroll
        for (int e = 0; e < 8; ++e) {
            hi[e] = tf32c(v[e]);
            lo[e] = tf32c(v[e] - __uint_as_float(hi[e]));
        }
    };
    auto store = [&](int c) {
        uint32_t* buf = smem + (c & 1) * BUFF;
        uint32_t hi[8], lo[8];
        split8(s0, s1, hi, lo);
        *(uint4*)&buf[r * ST + cb]            = *(uint4*)hi;
        *(uint4*)&buf[r * ST + cb + 4]        = *(uint4*)(hi + 4);
        *(uint4*)&buf[SLAB + r * ST + cb]     = *(uint4*)lo;
        *(uint4*)&buf[SLAB + r * ST + cb + 4] = *(uint4*)(lo + 4);
        split8(y0, y1, hi, lo);
        const int ry = 32 + r;
        *(uint4*)&buf[ry * ST + cb]            = *(uint4*)hi;
        *(uint4*)&buf[ry * ST + cb + 4]        = *(uint4*)(hi + 4);
        *(uint4*)&buf[SLAB + ry * ST + cb]     = *(uint4*)lo;
        *(uint4*)&buf[SLAB + ry * ST + cb + 4] = *(uint4*)(lo + 4);
        tw += dot4(s0, f0) + dot4(s1, f1);
        tu += dot4(y0, f0) + dot4(y1, f1);
    };

    ldregs(0); store(0); __syncthreads();

#pragma unroll 1
    for (int c = 0; c < NCH; ++c) {
        if (c + 1 < NCH) ldregs(c + 1);

        const uint32_t bufb = sbase + (uint32_t)(c & 1) * (BUFF * 4);
#pragma unroll
        for (int s2 = 0; s2 < 2; ++s2) {
            const uint32_t kbB = (uint32_t)((ks + s2 * 4) * 8) * 4u;
            uint32_t Ah[2][4], Al[2][4], Bh[2][4], Bl[2][4];
#pragma unroll
            for (int m = 0; m < 2; ++m) {
                LDMX4(Ah[m], bufb + offA[m] + kbB);
                LDMX4(Al[m], bufb + LOB + offA[m] + kbB);
            }
#pragma unroll
            for (int p = 0; p < 2; ++p) {
                LDMX4(Bh[p], bufb + offB[p] + kbB);
                LDMX4(Bl[p], bufb + LOB + offB[p] + kbB);
            }
#pragma unroll
            for (int m = 0; m < 2; ++m)
#pragma unroll
                for (int n = 0; n < 4; ++n) {
                    const int p = n >> 1, h = (n & 1) * 2;
                    MMA(acc[m][n], Ah[m], Bh[p][h], Bh[p][h + 1]);
                    MMA(acc[m][n], Ah[m], Bl[p][h], Bl[p][h + 1]);
                    MMA(acc[m][n], Al[m], Bh[p][h], Bh[p][h + 1]);
                }
        }

        if (c + 1 < NCH) store(c + 1);
        __syncthreads();
    }

    // writeback partials (per k-split; no cross-warp reduction)
    const int g = lane >> 2, q = lane & 3;
    float* out = gGp + (((size_t)kg * BB + b) * 4 + ks) * (64 * 32);
#pragma unroll
    for (int m = 0; m < 2; ++m) {
        const int R = (ms + m) * 16 + g;
#pragma unroll
        for (int n = 0; n < 4; ++n) {
            const int C = n * 8 + 2 * q;
            *(float2*)&out[R * 32 + C]       = make_float2(acc[m][n][0], acc[m][n][1]);
            *(float2*)&out[(R + 8) * 32 + C] = make_float2(acc[m][n][2], acc[m][n][3]);
        }
    }

    // w/u: reduce over the 8 lanes sharing loader-row r
#pragma unroll
    for (int off = 4; off > 0; off >>= 1) {
        tw += __shfl_xor_sync(0xffffffffu, tw, off);
        tu += __shfl_xor_sync(0xffffffffu, tu, off);
    }
    if ((lane & 7) == 0) {
        gwp[((size_t)kg * BB + b) * MM + r] = tw;
        gup[((size_t)kg * BB + b) * MM + r] = tu;
    }
}

__global__ __launch_bounds__(256)
void k2_solve(void) {
    __shared__ float sE[MM * MM];
    __shared__ float sF[MM * MM];
    const int b = blockIdx.x;
    const int tid = threadIdx.x;

#pragma unroll
    for (int e = 0; e < 4; ++e) {
        const int el = tid + e * 256;
        const int I = el >> 5, J = el & 31;
        float aE = 0.f, aF = 0.f;
#pragma unroll
        for (int p = 0; p < NKG * 4; ++p) {
            const int kg2 = p >> 2, ksp = p & 3;
            const float* Gb = gGp + (((size_t)kg2 * BB + b) * 4 + ksp) * (64 * 32);
            aE += Gb[I * 32 + J];
            aF += Gb[(32 + I) * 32 + J];
        }
        sE[el] = aE;
        sF[el] = aF;
    }
    __syncthreads();

    if (tid >= 32) return;
    const int j = tid;

    float w_own = 0.f, u_own = 0.f;
#pragma unroll
    for (int g = 0; g < NKG; ++g) {
        w_own += gwp[((size_t)g * BB + b) * MM + j];
        u_own += gup[((size_t)g * BB + b) * MM + j];
    }

    float ecol[MM];
#pragma unroll
    for (int i = 0; i < MM; ++i) ecol[i] = sE[i * MM + j];
    float a_own = 0.0f, r_own = 0.0f;
#pragma unroll
    for (int ii = 0; ii < MM; ++ii) {
        const int i = MM - 1 - ii;
        float contrib = (j > i) ? a_own * ecol[i] : 0.0f;
#pragma unroll
        for (int off = 16; off > 0; off >>= 1)
            contrib += __shfl_xor_sync(0xffffffffu, contrib, off);
        const float ediag = __shfl_sync(0xffffffffu, ecol[i], i);
        const float wi    = __shfl_sync(0xffffffffu, w_own, i);
        const float ai    = (-wi - contrib) / ediag;
        if (j == i) { a_own = ai; r_own = 1.0f / ediag; }
    }

    const float g = sE[(MM - 1) * MM + (MM - 1)] / sF[(MM - 1) * MM + (MM - 1)];

    float v_own = -u_own;
#pragma unroll
    for (int qq = 0; qq < 8; ++qq) {
        float4 fv = *(const float4*)&sF[j * MM + qq * 4];
        v_own -= __shfl_sync(0xffffffffu, a_own, qq * 4 + 0) * fv.x;
        v_own -= __shfl_sync(0xffffffffu, a_own, qq * 4 + 1) * fv.y;
        v_own -= __shfl_sync(0xffffffffu, a_own, qq * 4 + 2) * fv.z;
        v_own -= __shfl_sync(0xffffffffu, a_own, qq * 4 + 3) * fv.w;
    }

    float erow[MM];
#pragma unroll
    for (int qq = 0; qq < 8; ++qq) {
        float4 v = *(const float4*)&sE[j * MM + qq * 4];
        erow[qq * 4 + 0] = v.x; erow[qq * 4 + 1] = v.y;
        erow[qq * 4 + 2] = v.z; erow[qq * 4 + 3] = v.w;
    }
    float c_own = 0.0f;
#pragma unroll
    for (int i = 0; i < MM; ++i) {
        float contrib = (j < i) ? c_own * erow[i] : 0.0f;
#pragma unroll
        for (int off = 16; off > 0; off >>= 1)
            contrib += __shfl_xor_sync(0xffffffffu, contrib, off);
        const float ri = __shfl_sync(0xffffffffu, r_own, i);
        const float ai = __shfl_sync(0xffffffffu, a_own, i);
        const float vi = __shfl_sync(0xffffffffu, v_own, i);
        const float ci = ai - ri * (g * vi + contrib);
        if (j == i) c_own = ci;
    }

    gya[b * MM + j] = g * a_own;
    gcc[b * MM + j] = c_own;
    if (j == 0) gg[b] = g;
}

__global__ __launch_bounds__(256)
void k3_out(const float* __restrict__ S, const float* __restrict__ Y,
            const float* __restrict__ FRC, float* __restrict__ OUT) {
    __shared__ float sya[MM];
    __shared__ float scc[MM];
    __shared__ float sg[1];
    const int b  = blockIdx.x >> 3;
    const int ch = blockIdx.x & 7;
    const int tid = threadIdx.x;

    if (tid < MM) { sya[tid] = gya[b * MM + tid]; scc[tid] = gcc[b * MM + tid]; }
    if (tid == MM) sg[0] = gg[b];
    __syncthreads();

    const size_t d0 = (size_t)ch * CH3 + tid * 4;
    const float g = sg[0];
    float4 f = *(const float4*)(FRC + (size_t)b * DD + d0);
    u64 acc0 = pk2(g * f.x, g * f.y);
    u64 acc1 = pk2(g * f.z, g * f.w);

#pragma unroll
    for (int j = 0; j < MM; ++j) {
        ulonglong2 yv = *(const ulonglong2*)(Y + ((size_t)j * BB + b) * DD + d0);
        const float cv = sya[j];
        const u64 cc = pk2(cv, cv);
        acc0 = fma2(cc, yv.x, acc0);
        acc1 = fma2(cc, yv.y, acc1);
    }
#pragma unroll
    for (int i = 0; i < MM; ++i) {
        ulonglong2 sv = *(const ulonglong2*)(S + ((size_t)i * BB + b) * DD + d0);
        const float cv = -scc[i];
        const u64 cc = pk2(cv, cv);
        acc0 = fma2(cc, sv.x, acc0);
        acc1 = fma2(cc, sv.y, acc1);
    }

    float2 o0 = upk2(acc0), o1 = upk2(acc1);
    float4 o; o.x = o0.x; o.y = o0.y; o.z = o1.x; o.w = o1.y;
    *(float4*)(OUT + (size_t)b * DD + d0) = o;
}

extern "C" void kernel_launch(void* const* d_in, const int* in_sizes, int n_in,
                              void* d_out, int out_size) {
    const float* S   = (const float*)d_in[0];
    const float* Y   = (const float*)d_in[1];
    const float* FRC = (const float*)d_in[2];
    float* OUT = (float*)d_out;

    static bool attr_set = false;
    if (!attr_set) {
        cudaFuncSetAttribute(k1_gram,
                             cudaFuncAttributeMaxDynamicSharedMemorySize,
                             K1_SMEM);
        attr_set = true;
    }

    k1_gram<<<BB * NKG, 256, K1_SMEM>>>(S, Y, FRC);
    k2_solve<<<BB, 256>>>();
    k3_out<<<BB * NCH3, 256>>>(S, Y, FRC, OUT);
}

// round 17
// speedup vs baseline: 2.4788x; 1.0208x over previous
#include <cuda_runtime.h>
#include <cstdint>

// LBFGS via Gram reformulation; Gram via mma.sync tf32 + ldmatrix.
// R17: SMEM holds fp32 ONCE (no hi/lo slabs); ldmatrix fetches fp32 frags,
// Dekker split (hi=cvt.rna.tf32, lo=cvt(x-hi)) done in REGISTERS.
// Halves STS and LDSM traffic (L1 port was the binding pipe at 73.6%).

#define MM 32
#define BB 64
#define DD 8192
#define NKG 4
#define KSL (DD / NKG)
#define KC 64
#define NCH (KSL / KC)
#define ST 68
#define BUFF (64 * ST)          // one fp32 slab
#define K1_SMEM (2 * BUFF * 4)  // 34816 B
#define CH3 512
#define NCH3 (DD / CH3)         // 16

typedef unsigned long long u64;

__device__ float gGp[NKG * BB * 4 * 64 * 32];
__device__ float gwp[NKG * BB * MM];
__device__ float gup[NKG * BB * MM];
__device__ float gya[BB * MM];
__device__ float gcc[BB * MM];
__device__ float gg[BB];

__device__ __forceinline__ u64 pk2(float a, float b) {
    u64 r; asm("mov.b64 %0, {%1,%2};" : "=l"(r) : "f"(a), "f"(b)); return r;
}
__device__ __forceinline__ float2 upk2(u64 v) {
    float2 f; asm("mov.b64 {%0,%1}, %2;" : "=f"(f.x), "=f"(f.y) : "l"(v)); return f;
}
__device__ __forceinline__ u64 fma2(u64 a, u64 b, u64 c) {
    u64 d; asm("fma.rn.f32x2 %0, %1, %2, %3;" : "=l"(d) : "l"(a), "l"(b), "l"(c)); return d;
}
__device__ __forceinline__ float dot4(float4 a, float4 b) {
    return a.x * b.x + a.y * b.y + a.z * b.z + a.w * b.w;
}
__device__ __forceinline__ uint32_t tf32c(float x) {
    uint32_t r; asm("cvt.rna.tf32.f32 %0, %1;" : "=r"(r) : "f"(x)); return r;
}

#define LDMX4(R, addr) \
    asm volatile("ldmatrix.sync.aligned.m8n8.x4.shared.b16 {%0,%1,%2,%3},[%4];" \
        : "=r"((R)[0]), "=r"((R)[1]), "=r"((R)[2]), "=r"((R)[3]) : "r"(addr))

#define MMA(c, A, b0, b1) \
    asm volatile("mma.sync.aligned.m16n8k8.row.col.f32.tf32.tf32.f32 " \
        "{%0,%1,%2,%3},{%4,%5,%6,%7},{%8,%9},{%0,%1,%2,%3};" \
        : "+f"((c)[0]), "+f"((c)[1]), "+f"((c)[2]), "+f"((c)[3]) \
        : "r"((A)[0]), "r"((A)[1]), "r"((A)[2]), "r"((A)[3]), "r"(b0), "r"(b1))

// split 4 fp32 frag regs (bit patterns in u32) into tf32 hi/lo
__device__ __forceinline__ void split4(const uint32_t* f, uint32_t* hi, uint32_t* lo) {
#pragma unroll
    for (int e = 0; e < 4; ++e) {
        const float v = __uint_as_float(f[e]);
        hi[e] = tf32c(v);
        lo[e] = tf32c(v - __uint_as_float(hi[e]));
    }
}

__global__ __launch_bounds__(256, 2)
void k1_gram(const float* __restrict__ S, const float* __restrict__ Y,
             const float* __restrict__ FRC) {
    extern __shared__ __align__(16) uint32_t smem[];

    const int b    = blockIdx.x >> 2;
    const int kg   = blockIdx.x & 3;
    const int tid  = threadIdx.x;
    const int w    = tid >> 5;
    const int lane = tid & 31;
    const int ms   = (w & 1) * 2;
    const int ks   = w >> 1;

    // ldmatrix per-lane byte offsets (loop-invariant)
    const int mat = lane >> 3, rin = lane & 7;
    uint32_t offA[2], offB[2];
#pragma unroll
    for (int m = 0; m < 2; ++m)
        offA[m] = ((uint32_t)(((ms + m) * 16 + (mat & 1) * 8 + rin) * ST
                              + (mat >> 1) * 4)) * 4u;
#pragma unroll
    for (int p = 0; p < 2; ++p)
        offB[p] = ((uint32_t)((32 + (p * 2 + (mat >> 1)) * 8 + rin) * ST
                              + (mat & 1) * 4)) * 4u;
    const uint32_t sbase = (uint32_t)__cvta_generic_to_shared(smem);

    // loader role
    const int r  = tid >> 3;
    const int cb = (tid & 7) * 8;
    const size_t gS = ((size_t)r * BB + b) * DD + (size_t)kg * KSL + cb;
    const size_t gF = (size_t)b * DD + (size_t)kg * KSL + cb;

    float acc[2][4][4];
#pragma unroll
    for (int m = 0; m < 2; ++m)
#pragma unroll
        for (int n = 0; n < 4; ++n)
#pragma unroll
            for (int e = 0; e < 4; ++e) acc[m][n][e] = 0.0f;
    float tw = 0.f, tu = 0.f;

    float4 s0, s1, y0, y1, f0, f1;
    auto ldregs = [&](int c) {
        const size_t o = gS + (size_t)c * KC;
        s0 = *(const float4*)(S + o);     s1 = *(const float4*)(S + o + 4);
        y0 = *(const float4*)(Y + o);     y1 = *(const float4*)(Y + o + 4);
        const size_t of = gF + (size_t)c * KC;
        f0 = *(const float4*)(FRC + of);  f1 = *(const float4*)(FRC + of + 4);
    };
    auto store = [&](int c) {
        uint32_t* buf = smem + (c & 1) * BUFF;
        *(float4*)&buf[r * ST + cb]            = s0;
        *(float4*)&buf[r * ST + cb + 4]        = s1;
        *(float4*)&buf[(32 + r) * ST + cb]     = y0;
        *(float4*)&buf[(32 + r) * ST + cb + 4] = y1;
        tw += dot4(s0, f0) + dot4(s1, f1);
        tu += dot4(y0, f0) + dot4(y1, f1);
    };

    ldregs(0); store(0); __syncthreads();

#pragma unroll 1
    for (int c = 0; c < NCH; ++c) {
        if (c + 1 < NCH) ldregs(c + 1);

        const uint32_t bufb = sbase + (uint32_t)(c & 1) * (BUFF * 4);
#pragma unroll
        for (int s2 = 0; s2 < 2; ++s2) {
            const uint32_t kbB = (uint32_t)((ks + s2 * 4) * 8) * 4u;
            uint32_t Af[2][4], Bf[2][4];
            uint32_t Ah[2][4], Al[2][4], Bh[2][4], Bl[2][4];
#pragma unroll
            for (int m = 0; m < 2; ++m) {
                LDMX4(Af[m], bufb + offA[m] + kbB);
                split4(Af[m], Ah[m], Al[m]);
            }
#pragma unroll
            for (int p = 0; p < 2; ++p) {
                LDMX4(Bf[p], bufb + offB[p] + kbB);
                split4(Bf[p], Bh[p], Bl[p]);
            }
#pragma unroll
            for (int m = 0; m < 2; ++m)
#pragma unroll
                for (int n = 0; n < 4; ++n) {
                    const int p = n >> 1, h = (n & 1) * 2;
                    MMA(acc[m][n], Ah[m], Bh[p][h], Bh[p][h + 1]);
                    MMA(acc[m][n], Ah[m], Bl[p][h], Bl[p][h + 1]);
                    MMA(acc[m][n], Al[m], Bh[p][h], Bh[p][h + 1]);
                }
        }

        if (c + 1 < NCH) store(c + 1);
        __syncthreads();
    }

    // writeback partials (per k-split; no cross-warp reduction)
    const int g = lane >> 2, q = lane & 3;
    float* out = gGp + (((size_t)kg * BB + b) * 4 + ks) * (64 * 32);
#pragma unroll
    for (int m = 0; m < 2; ++m) {
        const int R = (ms + m) * 16 + g;
#pragma unroll
        for (int n = 0; n < 4; ++n) {
            const int C = n * 8 + 2 * q;
            *(float2*)&out[R * 32 + C]       = make_float2(acc[m][n][0], acc[m][n][1]);
            *(float2*)&out[(R + 8) * 32 + C] = make_float2(acc[m][n][2], acc[m][n][3]);
        }
    }

    // w/u: reduce over the 8 lanes sharing loader-row r
#pragma unroll
    for (int off = 4; off > 0; off >>= 1) {
        tw += __shfl_xor_sync(0xffffffffu, tw, off);
        tu += __shfl_xor_sync(0xffffffffu, tu, off);
    }
    if ((lane & 7) == 0) {
        gwp[((size_t)kg * BB + b) * MM + r] = tw;
        gup[((size_t)kg * BB + b) * MM + r] = tu;
    }
}

__global__ __launch_bounds__(256)
void k2_solve(void) {
    __shared__ float sE[MM * MM];
    __shared__ float sF[MM * MM];
    const int b = blockIdx.x;
    const int tid = threadIdx.x;

#pragma unroll
    for (int e = 0; e < 4; ++e) {
        const int el = tid + e * 256;
        const int I = el >> 5, J = el & 31;
        float aE = 0.f, aF = 0.f;
#pragma unroll
        for (int p = 0; p < NKG * 4; ++p) {
            const int kg2 = p >> 2, ksp = p & 3;
            const float* Gb = gGp + (((size_t)kg2 * BB + b) * 4 + ksp) * (64 * 32);
            aE += Gb[I * 32 + J];
            aF += Gb[(32 + I) * 32 + J];
        }
        sE[el] = aE;
        sF[el] = aF;
    }
    __syncthreads();

    if (tid >= 32) return;
    const int j = tid;

    float w_own = 0.f, u_own = 0.f;
#pragma unroll
    for (int g = 0; g < NKG; ++g) {
        w_own += gwp[((size_t)g * BB + b) * MM + j];
        u_own += gup[((size_t)g * BB + b) * MM + j];
    }

    float ecol[MM];
#pragma unroll
    for (int i = 0; i < MM; ++i) ecol[i] = sE[i * MM + j];
    float a_own = 0.0f, r_own = 0.0f;
#pragma unroll
    for (int ii = 0; ii < MM; ++ii) {
        const int i = MM - 1 - ii;
        float contrib = (j > i) ? a_own * ecol[i] : 0.0f;
#pragma unroll
        for (int off = 16; off > 0; off >>= 1)
            contrib += __shfl_xor_sync(0xffffffffu, contrib, off);
        const float ediag = __shfl_sync(0xffffffffu, ecol[i], i);
        const float wi    = __shfl_sync(0xffffffffu, w_own, i);
        const float ai    = (-wi - contrib) / ediag;
        if (j == i) { a_own = ai; r_own = 1.0f / ediag; }
    }

    const float g = sE[(MM - 1) * MM + (MM - 1)] / sF[(MM - 1) * MM + (MM - 1)];

    float v_own = -u_own;
#pragma unroll
    for (int qq = 0; qq < 8; ++qq) {
        float4 fv = *(const float4*)&sF[j * MM + qq * 4];
        v_own -= __shfl_sync(0xffffffffu, a_own, qq * 4 + 0) * fv.x;
        v_own -= __shfl_sync(0xffffffffu, a_own, qq * 4 + 1) * fv.y;
        v_own -= __shfl_sync(0xffffffffu, a_own, qq * 4 + 2) * fv.z;
        v_own -= __shfl_sync(0xffffffffu, a_own, qq * 4 + 3) * fv.w;
    }

    float erow[MM];
#pragma unroll
    for (int qq = 0; qq < 8; ++qq) {
        float4 v = *(const float4*)&sE[j * MM + qq * 4];
        erow[qq * 4 + 0] = v.x; erow[qq * 4 + 1] = v.y;
        erow[qq * 4 + 2] = v.z; erow[qq * 4 + 3] = v.w;
    }
    float c_own = 0.0f;
#pragma unroll
    for (int i = 0; i < MM; ++i) {
        float contrib = (j < i) ? c_own * erow[i] : 0.0f;
#pragma unroll
        for (int off = 16; off > 0; off >>= 1)
            contrib += __shfl_xor_sync(0xffffffffu, contrib, off);
        const float ri = __shfl_sync(0xffffffffu, r_own, i);
        const float ai = __shfl_sync(0xffffffffu, a_own, i);
        const float vi = __shfl_sync(0xffffffffu, v_own, i);
        const float ci = ai - ri * (g * vi + contrib);
        if (j == i) c_own = ci;
    }

    gya[b * MM + j] = g * a_own;
    gcc[b * MM + j] = c_own;
    if (j == 0) gg[b] = g;
}

__global__ __launch_bounds__(128)
void k3_out(const float* __restrict__ S, const float* __restrict__ Y,
            const float* __restrict__ FRC, float* __restrict__ OUT) {
    __shared__ float sya[MM];
    __shared__ float scc[MM];
    __shared__ float sg[1];
    const int b  = blockIdx.x >> 4;
    const int ch = blockIdx.x & 15;
    const int tid = threadIdx.x;

    if (tid < MM) { sya[tid] = gya[b * MM + tid]; scc[tid] = gcc[b * MM + tid]; }
    if (tid == MM) sg[0] = gg[b];
    __syncthreads();

    const size_t d0 = (size_t)ch * CH3 + tid * 4;
    const float g = sg[0];
    float4 f = *(const float4*)(FRC + (size_t)b * DD + d0);
    u64 acc0 = pk2(g * f.x, g * f.y);
    u64 acc1 = pk2(g * f.z, g * f.w);

#pragma unroll
    for (int j = 0; j < MM; ++j) {
        ulonglong2 yv = *(const ulonglong2*)(Y + ((size_t)j * BB + b) * DD + d0);
        const float cv = sya[j];
        const u64 cc = pk2(cv, cv);
        acc0 = fma2(cc, yv.x, acc0);
        acc1 = fma2(cc, yv.y, acc1);
    }
#pragma unroll
    for (int i = 0; i < MM; ++i) {
        ulonglong2 sv = *(const ulonglong2*)(S + ((size_t)i * BB + b) * DD + d0);
        const float cv = -scc[i];
        const u64 cc = pk2(cv, cv);
        acc0 = fma2(cc, sv.x, acc0);
        acc1 = fma2(cc, sv.y, acc1);
    }

    float2 o0 = upk2(acc0), o1 = upk2(acc1);
    float4 o; o.x = o0.x; o.y = o0.y; o.z = o1.x; o.w = o1.y;
    *(float4*)(OUT + (size_t)b * DD + d0) = o;
}

extern "C" void kernel_launch(void* const* d_in, const int* in_sizes, int n_in,
                              void* d_out, int out_size) {
    const float* S   = (const float*)d_in[0];
    const float* Y   = (const float*)d_in[1];
    const float* FRC = (const float*)d_in[2];
    float* OUT = (float*)d_out;

    static bool attr_set = false;
    if (!attr_set) {
        cudaFuncSetAttribute(k1_gram,
                             cudaFuncAttributeMaxDynamicSharedMemorySize,
                             K1_SMEM);
        attr_set = true;
    }

    k1_gram<<<BB * NKG, 256, K1_SMEM>>>(S, Y, FRC);
    k2_solve<<<BB, 256>>>();
    k3_out<<<BB * NCH3, 128>>>(S, Y, FRC, OUT);
}